// round 4
// baseline (speedup 1.0000x reference)
#include <cuda_runtime.h>
#include <math.h>

// Problem constants
#define Bc   2
#define Ac   4
#define Cc   3
#define Hc   32
#define Wc   32
#define HWc  (Hc*Wc)           // 1024
#define Nc   (HWc*Ac)          // 4096
#define NBC  (Bc*Cc)           // 6
#define LOG2E 1.4426950408889634f

// Scratch (device globals — no allocation allowed)
__device__ float4 g_box[Bc*Nc];        // BEV boxes (x1,y1,x2,y2)
__device__ float2 g_rec[NBC*Nc];       // (p1_j, sm_sc_j) per (b,c)
__device__ float  g_p0s[NBC*Nc];       // p0 * log2e per (b,c)
__device__ float  g_maxabs[NBC];       // max_j |p1_j| per (b,c)

__device__ __forceinline__ float ex2f(float x) {
    float y; asm("ex2.approx.f32 %0, %1;" : "=f"(y) : "f"(x)); return y;
}
__device__ __forceinline__ float warpMax(float v) {
    #pragma unroll
    for (int o = 16; o; o >>= 1) v = fmaxf(v, __shfl_xor_sync(0xffffffffu, v, o));
    return v;
}
__device__ __forceinline__ float warpSum(float v) {
    #pragma unroll
    for (int o = 16; o; o >>= 1) v += __shfl_xor_sync(0xffffffffu, v, o);
    return v;
}
// Block reduction (512 threads). sm must have >= 17 floats.
__device__ float blockReduce(float v, bool isMax, float* sm) {
    int tid = threadIdx.x, lane = tid & 31, w = tid >> 5;
    v = isMax ? warpMax(v) : warpSum(v);
    __syncthreads();
    if (lane == 0) sm[w] = v;
    __syncthreads();
    if (tid == 0) {
        float r = sm[0];
        int nw = blockDim.x >> 5;
        for (int i = 1; i < nw; i++) r = isMax ? fmaxf(r, sm[i]) : r + sm[i];
        sm[16] = r;
    }
    __syncthreads();
    return sm[16];
}

// ---- Kernel 1: decode nearest-BEV boxes ----
__global__ void boxes_kernel(const float* __restrict__ decoded) {
    int idx = blockIdx.x * blockDim.x + threadIdx.x;      // 0 .. B*N-1
    if (idx >= Bc * Nc) return;
    const float* d = decoded + (size_t)idx * 7;
    float x = d[0], y = d[1], d0 = d[3], d1 = d[4], rot = d[6];
    const float PIf  = 3.14159265358979323846f;
    const float PI4f = 0.78539816339744830962f;
    float k = floorf(rot / PIf + 0.5f);
    float normed = fabsf(rot - k * PIf);
    bool sw = normed > PI4f;
    float w = sw ? d1 : d0;
    float h = sw ? d0 : d1;
    g_box[idx] = make_float4(x - 0.5f * w, y - 0.5f * h, x + 0.5f * w, y + 0.5f * h);
}

// ---- Kernel 2: per-(b,c) score softmax over N, pack (p1, s), p0*log2e, max|p1| ----
__global__ void prep_kernel(const float* __restrict__ scores, const float* __restrict__ pp) {
    __shared__ float sm[17];
    int bc = blockIdx.x;              // 0..5
    int b = bc / Cc, c = bc % Cc;
    int tid = threadIdx.x;            // 512 threads, 8 elems each
    const float* sb = scores + b * (Ac * Cc * HWc);
    const float* pb = pp     + b * (Cc * 3 * HWc);
    float scv[8], p1v[8];
    float mx = -1e30f, ma = 0.f;
    #pragma unroll
    for (int k = 0; k < 8; k++) {
        int n = (k << 9) + tid;
        int hw = n >> 2, a = n & 3;
        float sc = sb[(a * Cc + c) * HWc + hw];
        float p0 = pb[(c * 3 + 0) * HWc + hw];
        float p1 = pb[(c * 3 + 1) * HWc + hw];
        g_p0s[bc * Nc + n] = p0 * LOG2E;
        scv[k] = sc; p1v[k] = p1;
        mx = fmaxf(mx, sc);
        ma = fmaxf(ma, fabsf(p1));
    }
    mx = blockReduce(mx, true, sm);
    ma = blockReduce(ma, true, sm);
    float ev[8], se = 0.f;
    #pragma unroll
    for (int k = 0; k < 8; k++) { ev[k] = expf(scv[k] - mx); se += ev[k]; }
    se = blockReduce(se, false, sm);
    float inv = 1.0f / se;
    #pragma unroll
    for (int k = 0; k < 8; k++) {
        int n = (k << 9) + tid;
        g_rec[bc * Nc + n] = make_float2(p1v[k], ev[k] * inv);
    }
    if (tid == 0) g_maxabs[bc] = ma;
}

// ---- Kernel 3: fused IoU + rank-1 logit + softmax-weighted aggregation ----
// One warp handles R=4 consecutive rows i of one (b,c); lanes stride over j.
#define RR 4
#define WARPS_PER_BLOCK 8
__global__ __launch_bounds__(256) void main_kernel(float* __restrict__ out) {
    int wid  = threadIdx.x >> 5, lane = threadIdx.x & 31;
    int wg   = blockIdx.x * WARPS_PER_BLOCK + wid;        // 0..6143
    int row0 = wg * RR;                                   // global row
    int bc   = row0 >> 12;                                // /4096
    int i0   = row0 & (Nc - 1);
    int b = bc / Cc, c = bc % Cc;

    const float4* __restrict__ boxB  = g_box + b * Nc;
    const float2* __restrict__ recBC = g_rec + bc * Nc;
    float maxabs = g_maxabs[bc];

    float bx1[RR], by1[RR], bx2[RR], by2[RR], ai[RR], p0s[RR], negM[RR];
    float lsum[RR], acc[RR];
    #pragma unroll
    for (int r = 0; r < RR; r++) {
        float4 bb = boxB[i0 + r];
        bx1[r] = bb.x; by1[r] = bb.y; bx2[r] = bb.z; by2[r] = bb.w;
        ai[r]  = (bb.z - bb.x) * (bb.w - bb.y);
        p0s[r] = g_p0s[bc * Nc + i0 + r];
        negM[r] = -fmaf(fabsf(p0s[r]), maxabs, LOG2E);    // -(log2e*1 + |p0s|*max|p1|)
        lsum[r] = 0.f; acc[r] = 0.f;
    }

    #pragma unroll 2
    for (int j = lane; j < Nc; j += 32) {
        float4 bj = __ldg(boxB + j);
        float2 rc = __ldg(recBC + j);
        float aj = (bj.z - bj.x) * (bj.w - bj.y);
        #pragma unroll
        for (int r = 0; r < RR; r++) {
            float lx = fmaxf(bx1[r], bj.x);
            float ly = fmaxf(by1[r], bj.y);
            float rx = fminf(bx2[r], bj.z);
            float ry = fminf(by2[r], bj.w);
            float w  = fmaxf(rx - lx, 0.f);
            float h  = fmaxf(ry - ly, 0.f);
            float inter = w * h;
            float uni   = (ai[r] + aj) - inter;           // union >= 0.25 > EPS always
            float rcu   = __fdividef(LOG2E, uni);         // log2e / union (MUFU rcp + mul)
            float t     = fmaf(p0s[r], rc.x, negM[r]);    // log2e*p0*p1 - M
            float L     = fmaf(inter, rcu, t);            // log2e*(iou + p0*p1) - M
            float p     = ex2f(L);
            lsum[r] += p;
            acc[r]   = fmaf(p, rc.y, acc[r]);
        }
    }

    #pragma unroll
    for (int r = 0; r < RR; r++) { lsum[r] = warpSum(lsum[r]); acc[r] = warpSum(acc[r]); }

    if (lane == 0) {
        #pragma unroll
        for (int r = 0; r < RR; r++) {
            int i = i0 + r;
            int a = i & 3, hw = i >> 2;
            out[b * (Ac * Cc * HWc) + (a * Cc + c) * HWc + hw] = acc[r] / lsum[r];
        }
    }
}

extern "C" void kernel_launch(void* const* d_in, const int* in_sizes, int n_in,
                              void* d_out, int out_size) {
    const float* scores  = (const float*)d_in[0];  // (2,12,32,32)  24576
    const float* bbox    = (const float*)d_in[1];  // (2,28,32,32)  57344
    const float* pp      = (const float*)d_in[2];  // (2,9,32,32)   18432
    const float* decoded = (const float*)d_in[3];  // (2,4096,7)    57344
    float* out = (float*)d_out;

    boxes_kernel<<<(Bc * Nc + 255) / 256, 256>>>(decoded);
    prep_kernel<<<NBC, 512>>>(scores, pp);

    // Total rows = B*C*N = 24576. Each block: 8 warps * RR rows = 32 rows.
    const int total_rows = Bc * Cc * Nc;                      // 24576
    const int rows_per_block = WARPS_PER_BLOCK * RR;          // 32
    const int blocks = total_rows / rows_per_block;           // 768  (FIXED: was /32 twice)
    main_kernel<<<blocks, 256>>>(out);

    // Pass-through outputs
    cudaMemcpyAsync(out + Bc * Ac * Cc * HWc, bbox,
                    (size_t)Bc * Ac * 7 * HWc * sizeof(float),
                    cudaMemcpyDeviceToDevice, 0);
    cudaMemcpyAsync(out + Bc * Ac * Cc * HWc + Bc * Ac * 7 * HWc, pp,
                    (size_t)Bc * Cc * 3 * HWc * sizeof(float),
                    cudaMemcpyDeviceToDevice, 0);
}

// round 5
// speedup vs baseline: 1.6410x; 1.6410x over previous
#include <cuda_runtime.h>
#include <math.h>

// Problem constants
#define Bc   2
#define Ac   4
#define Cc   3
#define HWc  1024
#define Nc   4096              // H*W*A
#define LOG2E 1.4426950408889634f

// Scratch (device globals — no allocation allowed)
__device__ float4 g_box[Bc*Nc];   // BEV boxes (x1,y1,x2,y2)
__device__ float4 g_p1v[Bc*Nc];   // p1 per class in .x/.y/.z
__device__ float4 g_smv[Bc*Nc];   // softmaxed score per class in .x/.y/.z
__device__ float4 g_p0s[Bc*Nc];   // p0*log2e per class in .x/.y/.z
__device__ float4 g_mab[Bc];      // max|p1*log2e|... (raw max|p1|) per class

__device__ __forceinline__ float ex2f(float x) {
    float y; asm("ex2.approx.f32 %0, %1;" : "=f"(y) : "f"(x)); return y;
}
__device__ __forceinline__ float warpMax(float v) {
    #pragma unroll
    for (int o = 16; o; o >>= 1) v = fmaxf(v, __shfl_xor_sync(0xffffffffu, v, o));
    return v;
}
__device__ __forceinline__ float warpSum(float v) {
    #pragma unroll
    for (int o = 16; o; o >>= 1) v += __shfl_xor_sync(0xffffffffu, v, o);
    return v;
}
__device__ float blockReduce(float v, bool isMax, float* sm) {
    int tid = threadIdx.x, lane = tid & 31, w = tid >> 5;
    v = isMax ? warpMax(v) : warpSum(v);
    __syncthreads();
    if (lane == 0) sm[w] = v;
    __syncthreads();
    if (tid == 0) {
        float r = sm[0];
        int nw = blockDim.x >> 5;
        for (int i = 1; i < nw; i++) r = isMax ? fmaxf(r, sm[i]) : r + sm[i];
        sm[16] = r;
    }
    __syncthreads();
    return sm[16];
}

// ---- Fused prologue kernel ----
// blocks 0..5   : per-(b,c) score softmax + pack p1/sm/p0s + max|p1|   (512 thr)
// blocks 6..21  : BEV box decode (16 blocks x 512 = 8192 rows)
// blocks 22..58 : pass-through float4 copies (bbox_preds, pp_params)   (18944 f4)
#define BBOX_F4 14336   // 2*28*1024 /4
#define PP_F4   4608    // 2*9*1024  /4
__global__ __launch_bounds__(512) void prologue_kernel(
    const float* __restrict__ scores, const float* __restrict__ pp,
    const float* __restrict__ decoded,
    const float4* __restrict__ bboxv, const float4* __restrict__ ppv,
    float4* __restrict__ out_bbox, float4* __restrict__ out_pp)
{
    int blk = blockIdx.x, tid = threadIdx.x;

    if (blk >= 22) {                       // pass-through copies
        int idx = (blk - 22) * 512 + tid;  // 0..18943
        if (idx < BBOX_F4) out_bbox[idx] = bboxv[idx];
        else               out_pp[idx - BBOX_F4] = ppv[idx - BBOX_F4];
        return;
    }
    if (blk >= 6) {                        // box decode
        int idx = (blk - 6) * 512 + tid;   // 0..8191
        const float* d = decoded + (size_t)idx * 7;
        float x = d[0], y = d[1], d0 = d[3], d1 = d[4], rot = d[6];
        const float PIf  = 3.14159265358979323846f;
        const float PI4f = 0.78539816339744830962f;
        float k = floorf(rot / PIf + 0.5f);
        float normed = fabsf(rot - k * PIf);
        bool sw = normed > PI4f;
        float w = sw ? d1 : d0;
        float h = sw ? d0 : d1;
        g_box[idx] = make_float4(x - 0.5f * w, y - 0.5f * h, x + 0.5f * w, y + 0.5f * h);
        return;
    }

    // prep: one block per (b,c)
    __shared__ float sm[17];
    int b = blk / Cc, c = blk % Cc;
    const float* sb = scores + b * (Ac * Cc * HWc);
    const float* pb = pp     + b * (Cc * 3 * HWc);
    float scv[8], p1v[8];
    float mx = -1e30f, ma = 0.f;
    #pragma unroll
    for (int k = 0; k < 8; k++) {
        int n = (k << 9) + tid;
        int hw = n >> 2, a = n & 3;
        float sc = sb[(a * Cc + c) * HWc + hw];
        float p0 = pb[(c * 3 + 0) * HWc + hw];
        float p1 = pb[(c * 3 + 1) * HWc + hw];
        ((float*)&g_p0s[b * Nc + n])[c] = p0 * LOG2E;
        ((float*)&g_p1v[b * Nc + n])[c] = p1;
        scv[k] = sc; p1v[k] = p1;
        mx = fmaxf(mx, sc);
        ma = fmaxf(ma, fabsf(p1));
    }
    mx = blockReduce(mx, true, sm);
    ma = blockReduce(ma, true, sm);
    float ev[8], se = 0.f;
    #pragma unroll
    for (int k = 0; k < 8; k++) { ev[k] = expf(scv[k] - mx); se += ev[k]; }
    se = blockReduce(se, false, sm);
    float inv = 1.0f / se;
    #pragma unroll
    for (int k = 0; k < 8; k++) {
        int n = (k << 9) + tid;
        ((float*)&g_smv[b * Nc + n])[c] = ev[k] * inv;
    }
    if (tid == 0) ((float*)&g_mab[b])[c] = ma;
}

// ---- Main kernel: IoU computed ONCE per (b,i,j), shared across 3 classes ----
// One warp handles RR=4 consecutive rows i of one batch b; lanes stride over j.
#define RR  4
#define WPB 2
__global__ __launch_bounds__(WPB*32) void main_kernel(float* __restrict__ out) {
    int wid  = threadIdx.x >> 5, lane = threadIdx.x & 31;
    int wg   = blockIdx.x * WPB + wid;        // 0..2047
    int row0 = wg * RR;                       // 0..8188
    int b    = row0 >> 12;
    int i0   = row0 & (Nc - 1);

    const float4* __restrict__ boxB = g_box + b * Nc;
    const float4* __restrict__ p1B  = g_p1v + b * Nc;
    const float4* __restrict__ smB  = g_smv + b * Nc;
    float4 mab = g_mab[b];

    float bx1[RR], by1[RR], bx2[RR], by2[RR], ai[RR];
    float p0s[RR][3], negM[RR][3], lsum[RR][3], acc[RR][3];
    #pragma unroll
    for (int r = 0; r < RR; r++) {
        float4 bb = boxB[i0 + r];
        bx1[r] = bb.x; by1[r] = bb.y; bx2[r] = bb.z; by2[r] = bb.w;
        ai[r]  = (bb.z - bb.x) * (bb.w - bb.y);
        float4 p0 = g_p0s[b * Nc + i0 + r];
        p0s[r][0] = p0.x; p0s[r][1] = p0.y; p0s[r][2] = p0.z;
        negM[r][0] = -fmaf(fabsf(p0.x), mab.x, LOG2E);   // -(log2e + |p0s|*max|p1|)
        negM[r][1] = -fmaf(fabsf(p0.y), mab.y, LOG2E);
        negM[r][2] = -fmaf(fabsf(p0.z), mab.z, LOG2E);
        #pragma unroll
        for (int c = 0; c < 3; c++) { lsum[r][c] = 0.f; acc[r][c] = 0.f; }
    }

    #pragma unroll 2
    for (int j = lane; j < Nc; j += 32) {
        float4 bj  = __ldg(boxB + j);
        float4 p1j = __ldg(p1B + j);
        float4 smj = __ldg(smB + j);
        float aj = (bj.z - bj.x) * (bj.w - bj.y);
        #pragma unroll
        for (int r = 0; r < RR; r++) {
            float lx = fmaxf(bx1[r], bj.x);
            float ly = fmaxf(by1[r], bj.y);
            float rx = fminf(bx2[r], bj.z);
            float ry = fminf(by2[r], bj.w);
            float w  = fmaxf(rx - lx, 0.f);
            float h  = fmaxf(ry - ly, 0.f);
            float inter = w * h;
            float uni   = (ai[r] + aj) - inter;           // union >= 0.25 always
            float rcu   = __fdividef(LOG2E, uni);         // log2e/union (MUFU rcp)
            // per-class: logit in log2 domain, bounded <= 0 by analytic max
            float t0 = fmaf(p0s[r][0], p1j.x, negM[r][0]);
            float t1 = fmaf(p0s[r][1], p1j.y, negM[r][1]);
            float t2 = fmaf(p0s[r][2], p1j.z, negM[r][2]);
            float p0e = ex2f(fmaf(inter, rcu, t0));
            float p1e = ex2f(fmaf(inter, rcu, t1));
            float p2e = ex2f(fmaf(inter, rcu, t2));
            lsum[r][0] += p0e;  acc[r][0] = fmaf(p0e, smj.x, acc[r][0]);
            lsum[r][1] += p1e;  acc[r][1] = fmaf(p1e, smj.y, acc[r][1]);
            lsum[r][2] += p2e;  acc[r][2] = fmaf(p2e, smj.z, acc[r][2]);
        }
    }

    #pragma unroll
    for (int r = 0; r < RR; r++)
        #pragma unroll
        for (int c = 0; c < 3; c++) {
            lsum[r][c] = warpSum(lsum[r][c]);
            acc[r][c]  = warpSum(acc[r][c]);
        }

    if (lane == 0) {
        #pragma unroll
        for (int r = 0; r < RR; r++) {
            int i = i0 + r;
            int a = i & 3, hw = i >> 2;
            #pragma unroll
            for (int c = 0; c < 3; c++)
                out[b * (Ac * Cc * HWc) + (a * Cc + c) * HWc + hw] = acc[r][c] / lsum[r][c];
        }
    }
}

extern "C" void kernel_launch(void* const* d_in, const int* in_sizes, int n_in,
                              void* d_out, int out_size) {
    const float* scores  = (const float*)d_in[0];  // (2,12,32,32)
    const float* bbox    = (const float*)d_in[1];  // (2,28,32,32)
    const float* pp      = (const float*)d_in[2];  // (2,9,32,32)
    const float* decoded = (const float*)d_in[3];  // (2,4096,7)
    float* out = (float*)d_out;

    float4* out_bbox = (float4*)(out + Bc * Ac * Cc * HWc);                     // +24576
    float4* out_pp   = (float4*)(out + Bc * Ac * Cc * HWc + Bc * Ac * 7 * HWc); // +81920

    // 6 prep + 16 boxes + 37 copy = 59 blocks
    prologue_kernel<<<59, 512>>>(scores, pp, decoded,
                                 (const float4*)bbox, (const float4*)pp,
                                 out_bbox, out_pp);

    // rows = B*N = 8192; RR=4 rows/warp, WPB=2 warps/block -> 1024 blocks
    main_kernel<<<(Bc * Nc) / (RR * WPB), WPB * 32>>>(out);
}

// round 6
// speedup vs baseline: 1.8035x; 1.0990x over previous
#include <cuda_runtime.h>
#include <math.h>

// Problem constants
#define Bc   2
#define Ac   4
#define Cc   3
#define HWc  1024
#define Nc   4096              // H*W*A
#define LOG2E 1.4426950408889634f

// Scratch (device globals — no allocation allowed)
__device__ float4 g_box[Bc*Nc];   // BEV boxes (x1,y1,x2,y2)
__device__ float4 g_p1v[Bc*Nc];   // p1 per class in .x/.y/.z
__device__ float4 g_smv[Bc*Nc];   // softmaxed score per class in .x/.y/.z
__device__ float4 g_p0s[Bc*Nc];   // p0*log2e per class in .x/.y/.z
__device__ float4 g_mab[Bc];      // max|p1| per class

__device__ __forceinline__ float ex2f(float x) {
    float y; asm("ex2.approx.f32 %0, %1;" : "=f"(y) : "f"(x)); return y;
}
__device__ __forceinline__ float warpMax(float v) {
    #pragma unroll
    for (int o = 16; o; o >>= 1) v = fmaxf(v, __shfl_xor_sync(0xffffffffu, v, o));
    return v;
}
__device__ __forceinline__ float warpSum(float v) {
    #pragma unroll
    for (int o = 16; o; o >>= 1) v += __shfl_xor_sync(0xffffffffu, v, o);
    return v;
}
__device__ float blockReduce(float v, bool isMax, float* sm) {
    int tid = threadIdx.x, lane = tid & 31, w = tid >> 5;
    v = isMax ? warpMax(v) : warpSum(v);
    __syncthreads();
    if (lane == 0) sm[w] = v;
    __syncthreads();
    if (tid == 0) {
        float r = sm[0];
        int nw = blockDim.x >> 5;
        for (int i = 1; i < nw; i++) r = isMax ? fmaxf(r, sm[i]) : r + sm[i];
        sm[16] = r;
    }
    __syncthreads();
    return sm[16];
}

// ---- Fused prologue kernel ----
// blocks 0..5   : per-(b,c) score softmax + pack p1/sm/p0s + max|p1|   (512 thr)
// blocks 6..21  : BEV box decode (16 blocks x 512 = 8192 rows)
// blocks 22..58 : pass-through float4 copies (bbox_preds, pp_params)
#define BBOX_F4 14336   // 2*28*1024 /4
#define PP_F4   4608    // 2*9*1024  /4
__global__ __launch_bounds__(512) void prologue_kernel(
    const float* __restrict__ scores, const float* __restrict__ pp,
    const float* __restrict__ decoded,
    const float4* __restrict__ bboxv, const float4* __restrict__ ppv,
    float4* __restrict__ out_bbox, float4* __restrict__ out_pp)
{
    int blk = blockIdx.x, tid = threadIdx.x;

    if (blk >= 22) {                       // pass-through copies
        int idx = (blk - 22) * 512 + tid;  // 0..18943
        if (idx < BBOX_F4) out_bbox[idx] = bboxv[idx];
        else               out_pp[idx - BBOX_F4] = ppv[idx - BBOX_F4];
        return;
    }
    if (blk >= 6) {                        // box decode
        int idx = (blk - 6) * 512 + tid;   // 0..8191
        const float* d = decoded + (size_t)idx * 7;
        float x = d[0], y = d[1], d0 = d[3], d1 = d[4], rot = d[6];
        const float PIf  = 3.14159265358979323846f;
        const float PI4f = 0.78539816339744830962f;
        float k = floorf(rot / PIf + 0.5f);
        float normed = fabsf(rot - k * PIf);
        bool sw = normed > PI4f;
        float w = sw ? d1 : d0;
        float h = sw ? d0 : d1;
        g_box[idx] = make_float4(x - 0.5f * w, y - 0.5f * h, x + 0.5f * w, y + 0.5f * h);
        return;
    }

    // prep: one block per (b,c)
    __shared__ float sm[17];
    int b = blk / Cc, c = blk % Cc;
    const float* sb = scores + b * (Ac * Cc * HWc);
    const float* pb = pp     + b * (Cc * 3 * HWc);
    float scv[8], p1v[8];
    float mx = -1e30f, ma = 0.f;
    #pragma unroll
    for (int k = 0; k < 8; k++) {
        int n = (k << 9) + tid;
        int hw = n >> 2, a = n & 3;
        float sc = sb[(a * Cc + c) * HWc + hw];
        float p0 = pb[(c * 3 + 0) * HWc + hw];
        float p1 = pb[(c * 3 + 1) * HWc + hw];
        ((float*)&g_p0s[b * Nc + n])[c] = p0 * LOG2E;
        ((float*)&g_p1v[b * Nc + n])[c] = p1;
        scv[k] = sc; p1v[k] = p1;
        mx = fmaxf(mx, sc);
        ma = fmaxf(ma, fabsf(p1));
    }
    mx = blockReduce(mx, true, sm);
    ma = blockReduce(ma, true, sm);
    float ev[8], se = 0.f;
    #pragma unroll
    for (int k = 0; k < 8; k++) { ev[k] = expf(scv[k] - mx); se += ev[k]; }
    se = blockReduce(se, false, sm);
    float inv = 1.0f / se;
    #pragma unroll
    for (int k = 0; k < 8; k++) {
        int n = (k << 9) + tid;
        ((float*)&g_smv[b * Nc + n])[c] = ev[k] * inv;
    }
    if (tid == 0) ((float*)&g_mab[b])[c] = ma;
}

// ---- Main kernel: IoU shared across 3 classes; RR=2 rows/warp for occupancy ----
#define RR  2
#define WPB 4
__global__ __launch_bounds__(WPB*32, 7) void main_kernel(float* __restrict__ out) {
    int wid  = threadIdx.x >> 5, lane = threadIdx.x & 31;
    int wg   = blockIdx.x * WPB + wid;        // 0..4095
    int row0 = wg * RR;                       // 0..8190
    int b    = row0 >> 12;
    int i0   = row0 & (Nc - 1);

    const float4* __restrict__ boxB = g_box + b * Nc;
    const float4* __restrict__ p1B  = g_p1v + b * Nc;
    const float4* __restrict__ smB  = g_smv + b * Nc;
    float4 mab = g_mab[b];

    float bx1[RR], by1[RR], bx2[RR], by2[RR], ai[RR];
    float p0s[RR][3], negM[RR][3], lsum[RR][3], acc[RR][3];
    #pragma unroll
    for (int r = 0; r < RR; r++) {
        float4 bb = boxB[i0 + r];
        bx1[r] = bb.x; by1[r] = bb.y; bx2[r] = bb.z; by2[r] = bb.w;
        ai[r]  = (bb.z - bb.x) * (bb.w - bb.y);
        float4 p0 = g_p0s[b * Nc + i0 + r];
        p0s[r][0] = p0.x; p0s[r][1] = p0.y; p0s[r][2] = p0.z;
        negM[r][0] = -fmaf(fabsf(p0.x), mab.x, LOG2E);   // -(log2e + |p0s|*max|p1|)
        negM[r][1] = -fmaf(fabsf(p0.y), mab.y, LOG2E);
        negM[r][2] = -fmaf(fabsf(p0.z), mab.z, LOG2E);
        #pragma unroll
        for (int c = 0; c < 3; c++) { lsum[r][c] = 0.f; acc[r][c] = 0.f; }
    }

    #pragma unroll 2
    for (int j = lane; j < Nc; j += 32) {
        float4 bj  = __ldg(boxB + j);
        float4 p1j = __ldg(p1B + j);
        float4 smj = __ldg(smB + j);
        float aj = (bj.z - bj.x) * (bj.w - bj.y);
        #pragma unroll
        for (int r = 0; r < RR; r++) {
            float lx = fmaxf(bx1[r], bj.x);
            float ly = fmaxf(by1[r], bj.y);
            float rx = fminf(bx2[r], bj.z);
            float ry = fminf(by2[r], bj.w);
            float w  = fmaxf(rx - lx, 0.f);
            float h  = fmaxf(ry - ly, 0.f);
            float inter = w * h;
            float uni   = (ai[r] + aj) - inter;           // union >= 0.25 always
            float rcu   = __fdividef(LOG2E, uni);         // MUFU rcp + mul
            float t0 = fmaf(p0s[r][0], p1j.x, negM[r][0]);
            float t1 = fmaf(p0s[r][1], p1j.y, negM[r][1]);
            float t2 = fmaf(p0s[r][2], p1j.z, negM[r][2]);
            float p0e = ex2f(fmaf(inter, rcu, t0));
            float p1e = ex2f(fmaf(inter, rcu, t1));
            float p2e = ex2f(fmaf(inter, rcu, t2));
            lsum[r][0] += p0e;  acc[r][0] = fmaf(p0e, smj.x, acc[r][0]);
            lsum[r][1] += p1e;  acc[r][1] = fmaf(p1e, smj.y, acc[r][1]);
            lsum[r][2] += p2e;  acc[r][2] = fmaf(p2e, smj.z, acc[r][2]);
        }
    }

    #pragma unroll
    for (int r = 0; r < RR; r++)
        #pragma unroll
        for (int c = 0; c < 3; c++) {
            lsum[r][c] = warpSum(lsum[r][c]);
            acc[r][c]  = warpSum(acc[r][c]);
        }

    if (lane == 0) {
        #pragma unroll
        for (int r = 0; r < RR; r++) {
            int i = i0 + r;
            int a = i & 3, hw = i >> 2;
            #pragma unroll
            for (int c = 0; c < 3; c++)
                out[b * (Ac * Cc * HWc) + (a * Cc + c) * HWc + hw] = acc[r][c] / lsum[r][c];
        }
    }
}

extern "C" void kernel_launch(void* const* d_in, const int* in_sizes, int n_in,
                              void* d_out, int out_size) {
    const float* scores  = (const float*)d_in[0];  // (2,12,32,32)
    const float* bbox    = (const float*)d_in[1];  // (2,28,32,32)
    const float* pp      = (const float*)d_in[2];  // (2,9,32,32)
    const float* decoded = (const float*)d_in[3];  // (2,4096,7)
    float* out = (float*)d_out;

    float4* out_bbox = (float4*)(out + Bc * Ac * Cc * HWc);
    float4* out_pp   = (float4*)(out + Bc * Ac * Cc * HWc + Bc * Ac * 7 * HWc);

    // 6 prep + 16 boxes + 37 copy = 59 blocks
    prologue_kernel<<<59, 512>>>(scores, pp, decoded,
                                 (const float4*)bbox, (const float4*)pp,
                                 out_bbox, out_pp);

    // rows = B*N = 8192; RR=2 rows/warp, WPB=4 warps/block -> 1024 blocks
    main_kernel<<<(Bc * Nc) / (RR * WPB), WPB * 32>>>(out);
}